// round 17
// baseline (speedup 1.0000x reference)
#include <cuda_runtime.h>
#include <cuda_bf16.h>
#include <math.h>

// ForwardBackwardImputer: out[b,t,:] = x[b, idx_fwd[b,t], :]
// mask[t] = all(|x[b,t,d]| <= 1e-6); idx_fwd = inclusive cummax(mask ? 0 : t).
// (Backward-fill branch of the reference is provably identical to x_fwd;
//  verified rel_err==0 across rounds.)
//
// Kernel A: each warp owns a CONTIGUOUS 64-row chunk (64 | L, so chunks never
//   cross batch rows). Rows are processed in 4-row groups with 4-deep MLP; a
//   per-lane float4 `carry` holds the last valid row, so every missing row
//   after the chunk's first valid row is filled HERE. Only the chunk's
//   leading missing run (E ~ 0.11 rows/chunk) stays unresolved; its length is
//   published as one int per chunk in g_run.
// Kernel B: tiny. One warp checks 32 chunks (lane-parallel + ballot); for
//   each chunk with run>0, the source is the last row of the nearest prior
//   chunk in the same batch row with run<64 (that row was finalized by A),
//   or the zero row at a batch-row start (reference maps leading-missing to
//   x[0] == zero row). Fills `run` rows from one gathered row.

#define L_SEQ 2048
#define D_FEAT 128
#define ROW_F4 (D_FEAT / 4)     // 32 float4 per timestep row
#define ATOL_F 1e-6f

#define A_THREADS 256
#define A_WARPS   8
#define CHUNK_GROUPS 16
#define CHUNK_ROWS   64         // divides L_SEQ -> no batch-row crossing
#define CHUNKS_PER_BATCHROW (L_SEQ / CHUNK_ROWS)   // 32

#define B_THREADS 256
#define B_WARPS   8

// Max problem we support: 1024 batch rows of 2048 steps -> 32768 chunks.
__device__ int g_run[32768];    // leading-missing-run length per chunk (0..64)

// ---------------- Kernel A: chunked mask+copy+carry-fill -------------------
__global__ __launch_bounds__(A_THREADS)
void phase_a_kernel(const float4* __restrict__ x, float4* __restrict__ out,
                    int nchunks) {
    const int lane = threadIdx.x & 31;
    const int w    = blockIdx.x * A_WARPS + (threadIdx.x >> 5);  // chunk id
    if (w >= nchunks) return;
    const unsigned FULL = 0xffffffffu;

    const int row0 = w * CHUNK_ROWS;     // first flattened row of this chunk

    float4 carry = make_float4(0.f, 0.f, 0.f, 0.f);
    bool have_carry = false;             // warp-uniform
    int run = 0;                         // leading missing run (warp-uniform)

    #pragma unroll 4
    for (int i = 0; i < CHUNK_GROUPS; i++) {
        const int r0 = row0 + (i << 2);
        float4 v0 = __ldcs(&x[(r0 + 0) * ROW_F4 + lane]);
        float4 v1 = __ldcs(&x[(r0 + 1) * ROW_F4 + lane]);
        float4 v2 = __ldcs(&x[(r0 + 2) * ROW_F4 + lane]);
        float4 v3 = __ldcs(&x[(r0 + 3) * ROW_F4 + lane]);

        bool z0 = (fabsf(v0.x) <= ATOL_F) & (fabsf(v0.y) <= ATOL_F) &
                  (fabsf(v0.z) <= ATOL_F) & (fabsf(v0.w) <= ATOL_F);
        bool z1 = (fabsf(v1.x) <= ATOL_F) & (fabsf(v1.y) <= ATOL_F) &
                  (fabsf(v1.z) <= ATOL_F) & (fabsf(v1.w) <= ATOL_F);
        bool z2 = (fabsf(v2.x) <= ATOL_F) & (fabsf(v2.y) <= ATOL_F) &
                  (fabsf(v2.z) <= ATOL_F) & (fabsf(v2.w) <= ATOL_F);
        bool z3 = (fabsf(v3.x) <= ATOL_F) & (fabsf(v3.y) <= ATOL_F) &
                  (fabsf(v3.z) <= ATOL_F) & (fabsf(v3.w) <= ATOL_F);

        unsigned m0 = __all_sync(FULL, z0);   // warp-uniform missing flags
        unsigned m1 = __all_sync(FULL, z1);
        unsigned m2 = __all_sync(FULL, z2);
        unsigned m3 = __all_sync(FULL, z3);

        // Sequential carry fill (branches are warp-uniform; selects only).
        if (!m0) { carry = v0; have_carry = true; __stcs(&out[(r0 + 0) * ROW_F4 + lane], v0); }
        else if (have_carry) { __stcs(&out[(r0 + 0) * ROW_F4 + lane], carry); }
        else run++;

        if (!m1) { carry = v1; have_carry = true; __stcs(&out[(r0 + 1) * ROW_F4 + lane], v1); }
        else if (have_carry) { __stcs(&out[(r0 + 1) * ROW_F4 + lane], carry); }
        else run++;

        if (!m2) { carry = v2; have_carry = true; __stcs(&out[(r0 + 2) * ROW_F4 + lane], v2); }
        else if (have_carry) { __stcs(&out[(r0 + 2) * ROW_F4 + lane], carry); }
        else run++;

        if (!m3) { carry = v3; have_carry = true; __stcs(&out[(r0 + 3) * ROW_F4 + lane], v3); }
        else if (have_carry) { __stcs(&out[(r0 + 3) * ROW_F4 + lane], carry); }
        else run++;
    }

    if (lane == 0) g_run[w] = run;
}

// ---------------- Kernel B: leading-run fill from chunk summaries ----------
__global__ __launch_bounds__(B_THREADS)
void phase_b_kernel(float4* __restrict__ out, int nchunks) {
    const int lane = threadIdx.x & 31;
    const int W    = blockIdx.x * B_WARPS + (threadIdx.x >> 5);
    const unsigned FULL = 0xffffffffu;

    const int cbase = W * 32;
    if (cbase >= nchunks) return;

    const int c_lane = cbase + lane;
    int r = (c_lane < nchunks) ? g_run[c_lane] : 0;
    unsigned bal = __ballot_sync(FULL, r > 0);

    const float4 zero = make_float4(0.f, 0.f, 0.f, 0.f);

    while (bal) {
        const int c = __ffs(bal) - 1;
        bal &= bal - 1u;
        const int chunk = cbase + c;
        const int rc = __shfl_sync(FULL, r, c);

        // Source = last row of nearest prior chunk (same batch row) with
        // run < CHUNK_ROWS; that row was finalized by kernel A. -1 => zeros.
        int src = -1;
        const int bfirst = (chunk / CHUNKS_PER_BATCHROW) * CHUNKS_PER_BATCHROW;
        for (int p = chunk - 1; p >= bfirst; p--) {
            if (g_run[p] < CHUNK_ROWS) { src = p * CHUNK_ROWS + CHUNK_ROWS - 1; break; }
        }

        float4 v = (src >= 0) ? out[src * ROW_F4 + lane] : zero;
        const int base = chunk * CHUNK_ROWS;
        for (int j = 0; j < rc; j++)
            __stcs(&out[(base + j) * ROW_F4 + lane], v);
    }
}

extern "C" void kernel_launch(void* const* d_in, const int* in_sizes, int n_in,
                              void* d_out, int out_size) {
    const float* x = (const float*)d_in[0];
    float* out = (float*)d_out;
    const int B = in_sizes[0] / (L_SEQ * D_FEAT);
    const int nchunks = B * CHUNKS_PER_BATCHROW;           // 8192 for B=256

    const int a_grid = (nchunks + A_WARPS - 1) / A_WARPS;  // 1024
    const int b_grid = (nchunks / 32 + B_WARPS - 1) / B_WARPS;  // 32

    phase_a_kernel<<<a_grid, A_THREADS>>>(
        reinterpret_cast<const float4*>(x),
        reinterpret_cast<float4*>(out), nchunks);
    phase_b_kernel<<<b_grid, B_THREADS>>>(
        reinterpret_cast<float4*>(out), nchunks);
}